// round 15
// baseline (speedup 1.0000x reference)
#include <cuda_runtime.h>
#include <cuda_bf16.h>
#include <cstdint>
#include <math.h>

#define B_ 256
#define M_ 64
#define N_ 32
#define D_ 128
#define T_ 64
#define L_ 128

// Scratch (allocation-free: __device__ globals)
__device__ __nv_bfloat16 g_xh[(size_t)M_ * B_ * D_];       // x hi, [m][b][d]
__device__ __nv_bfloat16 g_xl[(size_t)M_ * B_ * D_];       // x lo
__device__ __nv_bfloat16 g_wh[(size_t)M_ * N_ * T_ * D_];  // entmax W^T hi, [mn][t][d]
__device__ __nv_bfloat16 g_wl[(size_t)M_ * N_ * T_ * D_];  // entmax W^T lo
__device__ __nv_bfloat16 g_ph[(size_t)N_ * B_ * M_ * T_];  // priors hi, [n][b][m][t]
__device__ __nv_bfloat16 g_pl[(size_t)N_ * B_ * M_ * T_];  // priors lo
__device__ __nv_bfloat16 g_lhh[L_ * T_];                   // leaves hi, [l][t]
__device__ __nv_bfloat16 g_lhl[L_ * T_];                   // leaves lo

// pack (a,b) into bf16x2 hi word + bf16x2 lo-residual word
__device__ __forceinline__ void split2(float a, float b, unsigned& hi, unsigned& lo) {
    __nv_bfloat16 ha = __float2bfloat16(a), hb = __float2bfloat16(b);
    __nv_bfloat16 la = __float2bfloat16(a - __bfloat162float(ha));
    __nv_bfloat16 lb = __float2bfloat16(b - __bfloat162float(hb));
    hi = (unsigned)__bfloat16_as_ushort(ha) | ((unsigned)__bfloat16_as_ushort(hb) << 16);
    lo = (unsigned)__bfloat16_as_ushort(la) | ((unsigned)__bfloat16_as_ushort(lb) << 16);
}

// ---------------------------------------------------------------------------
// K0a: normalize routing_leaves rows; emit bf16 hi/lo [l][t]
// ---------------------------------------------------------------------------
__global__ void k_leaves(const float* __restrict__ leaves) {
    int l = threadIdx.x;
    if (l >= L_) return;
    float v[T_];
    float s = 0.f;
    #pragma unroll
    for (int t = 0; t < T_; ++t) { v[t] = leaves[l * T_ + t]; s = fmaf(v[t], v[t], s); }
    float inv = 1.0f / fmaxf(sqrtf(s), 1e-12f);
    #pragma unroll
    for (int t = 0; t < T_; ++t) {
        float f = v[t] * inv;
        __nv_bfloat16 h = __float2bfloat16(f);
        g_lhh[l * T_ + t] = h;
        g_lhl[l * T_ + t] = __float2bfloat16(f - __bfloat162float(h));
    }
}

// ---------------------------------------------------------------------------
// K0b: split x into bf16 hi/lo, transposed to [m][b][d]
// ---------------------------------------------------------------------------
__global__ __launch_bounds__(256) void k_xsplit(const float* __restrict__ x) {
    int m = blockIdx.x;
    for (int i = threadIdx.x; i < B_ * D_; i += 256) {
        int b = i >> 7, d = i & 127;
        float f = x[((size_t)b * M_ + m) * D_ + d];
        __nv_bfloat16 h = __float2bfloat16(f);
        size_t o = ((size_t)m * B_ + b) * D_ + d;
        g_xh[o] = h;
        g_xl[o] = __float2bfloat16(f - __bfloat162float(h));
    }
}

// ---------------------------------------------------------------------------
// K1: exact 1.5-entmax over D per (m,n,t) column via 12 bisection + 2 Newton.
//     2 threads/column. Emits W^T bf16 hi/lo [mn][t][d] directly from regs.
// ---------------------------------------------------------------------------
__global__ __launch_bounds__(128) void k_entmax(const float* __restrict__ rw) {
    __shared__ float sm[D_ * 65];
    int mn = blockIdx.x;
    const float* src = rw + (size_t)mn * D_ * T_;
    for (int i = threadIdx.x; i < D_ * T_; i += 128)
        sm[(i >> 6) * 65 + (i & 63)] = src[i];
    __syncthreads();

    int col = threadIdx.x >> 1, half = threadIdx.x & 1;
    float z[64];
    float mx = -3.0e38f;
    #pragma unroll
    for (int k = 0; k < 64; ++k) {
        z[k] = sm[(half * 64 + k) * 65 + col];
        mx = fmaxf(mx, z[k]);
    }
    mx = fmaxf(mx, __shfl_xor_sync(0xffffffffu, mx, 1));
    #pragma unroll
    for (int k = 0; k < 64; ++k) z[k] = 0.5f * z[k] - 0.5f * mx;

    float lo = -1.0f, hi = 0.0f;
    #pragma unroll 1
    for (int it = 0; it < 12; ++it) {
        float mid = 0.5f * (lo + hi);
        float s0 = 0.f, s1 = 0.f, s2 = 0.f, s3 = 0.f;
        #pragma unroll
        for (int k = 0; k < 64; k += 4) {
            float a0 = fmaxf(z[k + 0] - mid, 0.f); s0 = fmaf(a0, a0, s0);
            float a1 = fmaxf(z[k + 1] - mid, 0.f); s1 = fmaf(a1, a1, s1);
            float a2 = fmaxf(z[k + 2] - mid, 0.f); s2 = fmaf(a2, a2, s2);
            float a3 = fmaxf(z[k + 3] - mid, 0.f); s3 = fmaf(a3, a3, s3);
        }
        float s = (s0 + s1) + (s2 + s3);
        s += __shfl_xor_sync(0xffffffffu, s, 1);
        if (s >= 1.0f) lo = mid; else hi = mid;
    }
    float tau = 0.5f * (lo + hi);
    #pragma unroll 1
    for (int it = 0; it < 2; ++it) {
        float f0 = 0.f, f1 = 0.f, g0 = 0.f, g1 = 0.f;
        #pragma unroll
        for (int k = 0; k < 64; k += 2) {
            float a0 = fmaxf(z[k + 0] - tau, 0.f); f0 = fmaf(a0, a0, f0); g0 += a0;
            float a1 = fmaxf(z[k + 1] - tau, 0.f); f1 = fmaf(a1, a1, f1); g1 += a1;
        }
        float f = f0 + f1, g = g0 + g1;
        f += __shfl_xor_sync(0xffffffffu, f, 1);
        g += __shfl_xor_sync(0xffffffffu, g, 1);
        tau += (f - 1.0f) / fmaxf(2.0f * g, 1e-12f);
    }

    // W^T row = t (=col), d = half*64 + k; write hi/lo pairs straight out
    size_t base = ((size_t)mn * T_ + col) * D_ + half * 64;
    #pragma unroll
    for (int k = 0; k < 64; k += 2) {
        float a0 = fmaxf(z[k] - tau, 0.f);
        float a1 = fmaxf(z[k + 1] - tau, 0.f);
        unsigned h, l;
        split2(a0 * a0, a1 * a1, h, l);
        *(unsigned*)(g_wh + base + k) = h;
        *(unsigned*)(g_wl + base + k) = l;
    }
}

// ---------------------------------------------------------------------------
// K2: priors GEMM via mma.sync bf16, 3 hi/lo products.
//     One CTA per (m, b-chunk of 128): A = x[m][chunk] [128 b][128 d] hi/lo
//     staged once (272B rows, conflict-free); loop n = 0..31 staging
//     W^T[mn] [64 t][128 d] hi/lo and computing C[b,t]; epilogue splits acc
//     into priors bf16 hi/lo [n][b][m][t].
//     smem: Ah 0 | Al 34816 | Wh 69632 | Wl 87040 -> 104448 B.
// ---------------------------------------------------------------------------
#define KP_A_L 34816u
#define KP_WH  69632u
#define KP_WL  87040u
#define KP_SMEM 104448

__global__ __launch_bounds__(256) void k_priors_mma() {
    extern __shared__ __align__(16) char smc[];
    unsigned abase = (unsigned)__cvta_generic_to_shared(smc);
    int tid = threadIdx.x, lane = tid & 31, w = tid >> 5;
    int m = blockIdx.x >> 1, chunk = blockIdx.x & 1;

    // stage A (x hi/lo chunk)
    {
        const uint4* sh = (const uint4*)(g_xh + ((size_t)m * B_ + chunk * 128) * D_);
        const uint4* sl = (const uint4*)(g_xl + ((size_t)m * B_ + chunk * 128) * D_);
        for (int i = tid; i < 2048; i += 256) {
            int r = i >> 4, q = i & 15;
            *(uint4*)(smc + r * 272 + q * 16) = sh[i];
            *(uint4*)(smc + KP_A_L + r * 272 + q * 16) = sl[i];
        }
    }

    unsigned a_off = (unsigned)((w * 16 + (lane & 15)) * 272) + ((lane & 16) ? 16u : 0u);
    unsigned Ah_b = abase + a_off;
    unsigned Al_b = Ah_b + KP_A_L;
    unsigned b_row = (unsigned)((lane & 7) + ((lane & 16) ? 8 : 0));
    unsigned b_col = (lane & 8) ? 16u : 0u;
    unsigned Bh_b = abase + KP_WH + b_row * 272u + b_col;
    unsigned Bl_b = Bh_b + (KP_WL - KP_WH);

    #pragma unroll 1
    for (int n = 0; n < 32; ++n) {
        __syncthreads();  // previous iteration's W reads done (also orders A stage)
        {
            const uint4* wh = (const uint4*)(g_wh + (size_t)(m * 32 + n) * T_ * D_);
            const uint4* wl = (const uint4*)(g_wl + (size_t)(m * 32 + n) * T_ * D_);
            for (int i = tid; i < 1024; i += 256) {
                int r = i >> 4, q = i & 15;
                *(uint4*)(smc + KP_WH + r * 272 + q * 16) = wh[i];
                *(uint4*)(smc + KP_WL + r * 272 + q * 16) = wl[i];
            }
        }
        __syncthreads();

        float acc[8][4];
        #pragma unroll
        for (int nt = 0; nt < 8; ++nt)
            #pragma unroll
            for (int q = 0; q < 4; ++q) acc[nt][q] = 0.f;

        #pragma unroll 1
        for (int ks = 0; ks < 8; ++ks) {
            unsigned ra_h[4], ra_l[4];
            asm volatile("ldmatrix.sync.aligned.m8n8.x4.shared.b16 {%0,%1,%2,%3},[%4];"
                         : "=r"(ra_h[0]), "=r"(ra_h[1]), "=r"(ra_h[2]), "=r"(ra_h[3])
                         : "r"(Ah_b + (unsigned)ks * 32u));
            asm volatile("ldmatrix.sync.aligned.m8n8.x4.shared.b16 {%0,%1,%2,%3},[%4];"
                         : "=r"(ra_l[0]), "=r"(ra_l[1]), "=r"(ra_l[2]), "=r"(ra_l[3])
                         : "r"(Al_b + (unsigned)ks * 32u));
            #pragma unroll
            for (int np = 0; np < 4; ++np) {
                unsigned rb_h[4], rb_l[4];
                unsigned boff = (unsigned)np * 4352u + (unsigned)ks * 32u;  // 16*272
                asm volatile("ldmatrix.sync.aligned.m8n8.x4.shared.b16 {%0,%1,%2,%3},[%4];"
                             : "=r"(rb_h[0]), "=r"(rb_h[1]), "=r"(rb_h[2]), "=r"(rb_h[3])
                             : "r"(Bh_b + boff));
                asm volatile("ldmatrix.sync.aligned.m8n8.x4.shared.b16 {%0,%1,%2,%3},[%4];"
                             : "=r"(rb_l[0]), "=r"(rb_l[1]), "=r"(rb_l[2]), "=r"(rb_l[3])
                             : "r"(Bl_b + boff));
                #pragma unroll
                for (int h = 0; h < 2; ++h) {
                    float* A0 = acc[2 * np + h];
                    asm volatile(
                        "mma.sync.aligned.m16n8k16.row.col.f32.bf16.bf16.f32 "
                        "{%0,%1,%2,%3},{%4,%5,%6,%7},{%8,%9},{%0,%1,%2,%3};"
                        : "+f"(A0[0]), "+f"(A0[1]), "+f"(A0[2]), "+f"(A0[3])
                        : "r"(ra_h[0]), "r"(ra_h[1]), "r"(ra_h[2]), "r"(ra_h[3]),
                          "r"(rb_h[2 * h]), "r"(rb_h[2 * h + 1]));
                    asm volatile(
                        "mma.sync.aligned.m16n8k16.row.col.f32.bf16.bf16.f32 "
                        "{%0,%1,%2,%3},{%4,%5,%6,%7},{%8,%9},{%0,%1,%2,%3};"
                        : "+f"(A0[0]), "+f"(A0[1]), "+f"(A0[2]), "+f"(A0[3])
                        : "r"(ra_h[0]), "r"(ra_h[1]), "r"(ra_h[2]), "r"(ra_h[3]),
                          "r"(rb_l[2 * h]), "r"(rb_l[2 * h + 1]));
                    asm volatile(
                        "mma.sync.aligned.m16n8k16.row.col.f32.bf16.bf16.f32 "
                        "{%0,%1,%2,%3},{%4,%5,%6,%7},{%8,%9},{%0,%1,%2,%3};"
                        : "+f"(A0[0]), "+f"(A0[1]), "+f"(A0[2]), "+f"(A0[3])
                        : "r"(ra_l[0]), "r"(ra_l[1]), "r"(ra_l[2]), "r"(ra_l[3]),
                          "r"(rb_h[2 * h]), "r"(rb_h[2 * h + 1]));
                }
            }
        }

        // epilogue: split & store priors hi/lo [n][b][m][t]
        {
            int r0 = w * 16 + (lane >> 2);          // local b row
            int b = chunk * 128 + r0;
            size_t pb = (((size_t)n * B_ + b) * M_ + m) * T_;
            #pragma unroll
            for (int nt = 0; nt < 8; ++nt) {
                int c = nt * 8 + (lane & 3) * 2;
                unsigned h0, l0, h1, l1;
                split2(acc[nt][0], acc[nt][1], h0, l0);
                split2(acc[nt][2], acc[nt][3], h1, l1);
                *(unsigned*)(g_ph + pb + c) = h0;
                *(unsigned*)(g_pl + pb + c) = l0;
                *(unsigned*)(g_ph + pb + 8 * (size_t)(M_ * T_) + c) = h1;  // b+8
                *(unsigned*)(g_pl + pb + 8 * (size_t)(M_ * T_) + c) = l1;
            }
        }
    }
}

// ---------------------------------------------------------------------------
// K3: votes GEMM via mma.sync (unchanged from R14, validated).
//     One CTA per (n, b-pair): 256 threads / 8 warps, M=128 (2b x 64m),
//     N=128 l, K=64 t, 3 hi/lo products fused per fragment-load.
//     Votes in registers; vbar via shfl + warp table; dispersion via shfl.
// ---------------------------------------------------------------------------
#define K3_SMEM 80384

__global__ __launch_bounds__(256) void k_route(
    const float* __restrict__ thr, const float* __restrict__ gamma,
    const float* __restrict__ beta, float* __restrict__ out)
{
    extern __shared__ __align__(16) char smc[];
    unsigned abase = (unsigned)__cvta_generic_to_shared(smc);

    float* table = (float*)(smc + 73728);   // [8 warps][128 l]
    float* vbar  = (float*)(smc + 77824);   // [2][128]
    float* wgt   = (float*)(smc + 78848);   // [128]
    float* prob  = (float*)(smc + 79360);   // [128]
    float* ncs   = (float*)(smc + 79872);   // [128]

    int tid = threadIdx.x;
    int lane = tid & 31, w = tid >> 5;
    int n = blockIdx.x >> 7, bp = blockIdx.x & 127;

    {
        size_t pbase = (((size_t)n * B_ + 2 * bp) * M_) * T_;
        const uint4* sh = (const uint4*)(g_ph + pbase);
        const uint4* sl = (const uint4*)(g_pl + pbase);
        for (int i = tid; i < 1024; i += 256) {
            int r = i >> 3, q = i & 7;
            *(uint4*)(smc + r * 144 + q * 16) = sh[i];
            *(uint4*)(smc + 18432 + r * 144 + q * 16) = sl[i];
        }
        const uint4* th = (const uint4*)g_lhh;
        const uint4* tl = (const uint4*)g_lhl;
        for (int i = tid; i < 1024; i += 256) {
            int r = i >> 3, q = i & 7;
            *(uint4*)(smc + 36864 + r * 144 + q * 16) = th[i];
            *(uint4*)(smc + 55296 + r * 144 + q * 16) = tl[i];
        }
    }
    __syncthreads();

    int m0 = w * 16;
    unsigned a_off = (unsigned)((m0 + (lane & 15)) * 144) + ((lane & 16) ? 16u : 0u);
    unsigned Ah_b = abase + a_off;
    unsigned Al_b = abase + 18432u + a_off;
    unsigned b_row = (unsigned)((lane & 7) + ((lane & 16) ? 8 : 0));
    unsigned b_col = (lane & 8) ? 16u : 0u;
    unsigned Bh_b = abase + 36864u + b_row * 144u + b_col;
    unsigned Bl_b = Bh_b + 18432u;

    float acc[16][4];
    #pragma unroll
    for (int nt = 0; nt < 16; ++nt)
        #pragma unroll
        for (int q = 0; q < 4; ++q) acc[nt][q] = 0.f;

    #pragma unroll 1
    for (int ks = 0; ks < 4; ++ks) {
        unsigned ra_h[4], ra_l[4];
        asm volatile("ldmatrix.sync.aligned.m8n8.x4.shared.b16 {%0,%1,%2,%3},[%4];"
                     : "=r"(ra_h[0]), "=r"(ra_h[1]), "=r"(ra_h[2]), "=r"(ra_h[3])
                     : "r"(Ah_b + (unsigned)ks * 32u));
        asm volatile("ldmatrix.sync.aligned.m8n8.x4.shared.b16 {%0,%1,%2,%3},[%4];"
                     : "=r"(ra_l[0]), "=r"(ra_l[1]), "=r"(ra_l[2]), "=r"(ra_l[3])
                     : "r"(Al_b + (unsigned)ks * 32u));
        #pragma unroll
        for (int np = 0; np < 8; ++np) {
            unsigned rb_h[4], rb_l[4];
            unsigned boff = (unsigned)np * 2304u + (unsigned)ks * 32u;
            asm volatile("ldmatrix.sync.aligned.m8n8.x4.shared.b16 {%0,%1,%2,%3},[%4];"
                         : "=r"(rb_h[0]), "=r"(rb_h[1]), "=r"(rb_h[2]), "=r"(rb_h[3])
                         : "r"(Bh_b + boff));
            asm volatile("ldmatrix.sync.aligned.m8n8.x4.shared.b16 {%0,%1,%2,%3},[%4];"
                         : "=r"(rb_l[0]), "=r"(rb_l[1]), "=r"(rb_l[2]), "=r"(rb_l[3])
                         : "r"(Bl_b + boff));
            #pragma unroll
            for (int h = 0; h < 2; ++h) {
                float* A0 = acc[2 * np + h];
                asm volatile(
                    "mma.sync.aligned.m16n8k16.row.col.f32.bf16.bf16.f32 "
                    "{%0,%1,%2,%3},{%4,%5,%6,%7},{%8,%9},{%0,%1,%2,%3};"
                    : "+f"(A0[0]), "+f"(A0[1]), "+f"(A0[2]), "+f"(A0[3])
                    : "r"(ra_h[0]), "r"(ra_h[1]), "r"(ra_h[2]), "r"(ra_h[3]),
                      "r"(rb_h[2 * h]), "r"(rb_h[2 * h + 1]));
                asm volatile(
                    "mma.sync.aligned.m16n8k16.row.col.f32.bf16.bf16.f32 "
                    "{%0,%1,%2,%3},{%4,%5,%6,%7},{%8,%9},{%0,%1,%2,%3};"
                    : "+f"(A0[0]), "+f"(A0[1]), "+f"(A0[2]), "+f"(A0[3])
                    : "r"(ra_h[0]), "r"(ra_h[1]), "r"(ra_h[2]), "r"(ra_h[3]),
                      "r"(rb_l[2 * h]), "r"(rb_l[2 * h + 1]));
                asm volatile(
                    "mma.sync.aligned.m16n8k16.row.col.f32.bf16.bf16.f32 "
                    "{%0,%1,%2,%3},{%4,%5,%6,%7},{%8,%9},{%0,%1,%2,%3};"
                    : "+f"(A0[0]), "+f"(A0[1]), "+f"(A0[2]), "+f"(A0[3])
                    : "r"(ra_l[0]), "r"(ra_l[1]), "r"(ra_l[2]), "r"(ra_l[3]),
                      "r"(rb_h[2 * h]), "r"(rb_h[2 * h + 1]));
            }
        }
    }

    #pragma unroll
    for (int nt = 0; nt < 16; ++nt)
        #pragma unroll
        for (int q = 0; q < 4; ++q)
            acc[nt][q] = 1.0f / (1.0f + __expf(-acc[nt][q]));

    {
        float cs0[16], cs1[16];
        #pragma unroll
        for (int nt = 0; nt < 16; ++nt) {
            cs0[nt] = acc[nt][0] + acc[nt][2];
            cs1[nt] = acc[nt][1] + acc[nt][3];
        }
        #pragma unroll
        for (int s = 4; s <= 16; s <<= 1)
            #pragma unroll
            for (int nt = 0; nt < 16; ++nt) {
                cs0[nt] += __shfl_xor_sync(0xffffffffu, cs0[nt], s);
                cs1[nt] += __shfl_xor_sync(0xffffffffu, cs1[nt], s);
            }
        if (lane < 4) {
            #pragma unroll
            for (int nt = 0; nt < 16; ++nt)
                *(float2*)(table + w * 128 + nt * 8 + lane * 2) = make_float2(cs0[nt], cs1[nt]);
        }
    }
    __syncthreads();

    {
        int bb = tid >> 7, l = tid & 127;
        float s = table[(bb * 4 + 0) * 128 + l] + table[(bb * 4 + 1) * 128 + l]
                + table[(bb * 4 + 2) * 128 + l] + table[(bb * 4 + 3) * 128 + l];
        vbar[bb * 128 + l] = s * (1.0f / 64.0f);
    }
    __syncthreads();

    {
        int bb = w >> 2;
        float dis0 = 0.f, dis1 = 0.f;
        #pragma unroll
        for (int nt = 0; nt < 16; ++nt) {
            int c = nt * 8 + (lane & 3) * 2;
            float2 vb = *(const float2*)(vbar + bb * 128 + c);
            float d;
            d = acc[nt][0] - vb.x; dis0 = fmaf(d, d, dis0);
            d = acc[nt][1] - vb.y; dis0 = fmaf(d, d, dis0);
            d = acc[nt][2] - vb.x; dis1 = fmaf(d, d, dis1);
            d = acc[nt][3] - vb.y; dis1 = fmaf(d, d, dis1);
        }
        dis0 += __shfl_xor_sync(0xffffffffu, dis0, 1);
        dis0 += __shfl_xor_sync(0xffffffffu, dis0, 2);
        dis1 += __shfl_xor_sync(0xffffffffu, dis1, 1);
        dis1 += __shfl_xor_sync(0xffffffffu, dis1, 2);
        if ((lane & 3) == 0) {
            int row0 = m0 + (lane >> 2);
            float tw0 = thr[(row0 & 63) * N_ + n];
            float tw1 = thr[((row0 + 8) & 63) * N_ + n];
            wgt[row0]     = fmaxf(fmaf(tw0, tw0, -dis0 * (1.0f / L_)), 0.0f);
            wgt[row0 + 8] = fmaxf(fmaf(tw1, tw1, -dis1 * (1.0f / L_)), 0.0f);
        }
    }
    __syncthreads();

    if (tid < 128) {
        int bb = tid >> 6;
        float mxw = -3.0e38f;
        #pragma unroll 8
        for (int mm = 0; mm < 64; ++mm) mxw = fmaxf(mxw, wgt[bb * 64 + mm]);
        prob[tid] = __expf(wgt[tid] - mxw);
    }
    __syncthreads();

    if (tid < 128) {
        int bb = tid >> 6, t = tid & 63;
        const __nv_bfloat16* Ah = (const __nv_bfloat16*)smc;
        const __nv_bfloat16* Al = (const __nv_bfloat16*)(smc + 18432);
        float psum = 0.f;
        #pragma unroll 8
        for (int mm = 0; mm < 64; ++mm) psum += prob[bb * 64 + mm];
        float nc = 0.f;
        #pragma unroll 4
        for (int mm = 0; mm < 64; ++mm) {
            int row = bb * 64 + mm;
            float p = __bfloat162float(Ah[row * 72 + t]) + __bfloat162float(Al[row * 72 + t]);
            nc = fmaf(prob[bb * 64 + mm], p, nc);
        }
        ncs[tid] = nc / psum;
    }
    __syncthreads();

    if (tid < 128) {
        int bb = tid >> 6, t = tid & 63;
        float mu = 0.f;
        #pragma unroll 8
        for (int t2 = 0; t2 < T_; ++t2) mu += ncs[bb * 64 + t2];
        mu *= (1.0f / T_);
        float var = 0.f;
        #pragma unroll 8
        for (int t2 = 0; t2 < T_; ++t2) {
            float dv = ncs[bb * 64 + t2] - mu;
            var = fmaf(dv, dv, var);
        }
        var *= (1.0f / T_);
        float y = (ncs[tid] - mu) * rsqrtf(var + 1e-5f) * gamma[t] + beta[t];
        out[((size_t)(2 * bp + bb) * N_ + n) * T_ + t] = y;
    }
}

// ---------------------------------------------------------------------------
// Launch
// ---------------------------------------------------------------------------
extern "C" void kernel_launch(void* const* d_in, const int* in_sizes, int n_in,
                              void* d_out, int out_size) {
    const float* x      = (const float*)d_in[0];
    const float* rw     = (const float*)d_in[1];
    const float* thr    = (const float*)d_in[2];
    const float* leaves = (const float*)d_in[3];
    const float* gamma  = (const float*)d_in[4];
    const float* beta   = (const float*)d_in[5];
    float* out = (float*)d_out;

    static int attr_set = 0;
    if (!attr_set) {
        cudaFuncSetAttribute(k_priors_mma, cudaFuncAttributeMaxDynamicSharedMemorySize, KP_SMEM);
        cudaFuncSetAttribute(k_route, cudaFuncAttributeMaxDynamicSharedMemorySize, K3_SMEM);
        attr_set = 1;
    }

    k_leaves<<<1, 128>>>(leaves);
    k_xsplit<<<M_, 256>>>(x);
    k_entmax<<<M_ * N_, 128>>>(rw);
    k_priors_mma<<<M_ * 2, 256, KP_SMEM>>>();
    k_route<<<N_ * 128, 256, K3_SMEM>>>(thr, gamma, beta, out);
}

// round 16
// speedup vs baseline: 1.1825x; 1.1825x over previous
#include <cuda_runtime.h>
#include <cuda_bf16.h>
#include <cstdint>
#include <math.h>

#define B_ 256
#define M_ 64
#define N_ 32
#define D_ 128
#define T_ 64
#define L_ 128

// Scratch (allocation-free: __device__ globals)
__device__ __nv_bfloat16 g_xh[(size_t)M_ * B_ * D_];       // x hi, [m][b][d]
__device__ __nv_bfloat16 g_xl[(size_t)M_ * B_ * D_];       // x lo
__device__ __nv_bfloat16 g_wh[(size_t)M_ * N_ * T_ * D_];  // entmax W^T hi, [mn][t][d]
__device__ __nv_bfloat16 g_wl[(size_t)M_ * N_ * T_ * D_];  // entmax W^T lo
__device__ __nv_bfloat16 g_ph[(size_t)N_ * B_ * M_ * T_];  // priors hi, [n][b][m][t]
__device__ __nv_bfloat16 g_pl[(size_t)N_ * B_ * M_ * T_];  // priors lo
__device__ __nv_bfloat16 g_lhh[L_ * T_];                   // leaves hi, [l][t]
__device__ __nv_bfloat16 g_lhl[L_ * T_];                   // leaves lo

// pack (a,b) into bf16x2 hi word + bf16x2 lo-residual word
__device__ __forceinline__ void split2(float a, float b, unsigned& hi, unsigned& lo) {
    __nv_bfloat16 ha = __float2bfloat16(a), hb = __float2bfloat16(b);
    __nv_bfloat16 la = __float2bfloat16(a - __bfloat162float(ha));
    __nv_bfloat16 lb = __float2bfloat16(b - __bfloat162float(hb));
    hi = (unsigned)__bfloat16_as_ushort(ha) | ((unsigned)__bfloat16_as_ushort(hb) << 16);
    lo = (unsigned)__bfloat16_as_ushort(la) | ((unsigned)__bfloat16_as_ushort(lb) << 16);
}

// ---------------------------------------------------------------------------
// K0a: normalize routing_leaves rows; emit bf16 hi/lo [l][t]
// ---------------------------------------------------------------------------
__global__ void k_leaves(const float* __restrict__ leaves) {
    int l = threadIdx.x;
    if (l >= L_) return;
    float v[T_];
    float s = 0.f;
    #pragma unroll
    for (int t = 0; t < T_; ++t) { v[t] = leaves[l * T_ + t]; s = fmaf(v[t], v[t], s); }
    float inv = 1.0f / fmaxf(sqrtf(s), 1e-12f);
    #pragma unroll
    for (int t = 0; t < T_; ++t) {
        float f = v[t] * inv;
        __nv_bfloat16 h = __float2bfloat16(f);
        g_lhh[l * T_ + t] = h;
        g_lhl[l * T_ + t] = __float2bfloat16(f - __bfloat162float(h));
    }
}

// ---------------------------------------------------------------------------
// K0b: split x into bf16 hi/lo, transposed to [m][b][d]
// ---------------------------------------------------------------------------
__global__ __launch_bounds__(256) void k_xsplit(const float* __restrict__ x) {
    int m = blockIdx.x;
    for (int i = threadIdx.x; i < B_ * D_; i += 256) {
        int b = i >> 7, d = i & 127;
        float f = x[((size_t)b * M_ + m) * D_ + d];
        __nv_bfloat16 h = __float2bfloat16(f);
        size_t o = ((size_t)m * B_ + b) * D_ + d;
        g_xh[o] = h;
        g_xl[o] = __float2bfloat16(f - __bfloat162float(h));
    }
}

// ---------------------------------------------------------------------------
// K1: exact 1.5-entmax over D per (m,n,t) column via 12 bisection + 2 Newton.
//     2 threads/column. Emits W^T bf16 hi/lo [mn][t][d] directly from regs.
// ---------------------------------------------------------------------------
__global__ __launch_bounds__(128) void k_entmax(const float* __restrict__ rw) {
    __shared__ float sm[D_ * 65];
    int mn = blockIdx.x;
    const float* src = rw + (size_t)mn * D_ * T_;
    for (int i = threadIdx.x; i < D_ * T_; i += 128)
        sm[(i >> 6) * 65 + (i & 63)] = src[i];
    __syncthreads();

    int col = threadIdx.x >> 1, half = threadIdx.x & 1;
    float z[64];
    float mx = -3.0e38f;
    #pragma unroll
    for (int k = 0; k < 64; ++k) {
        z[k] = sm[(half * 64 + k) * 65 + col];
        mx = fmaxf(mx, z[k]);
    }
    mx = fmaxf(mx, __shfl_xor_sync(0xffffffffu, mx, 1));
    #pragma unroll
    for (int k = 0; k < 64; ++k) z[k] = 0.5f * z[k] - 0.5f * mx;

    float lo = -1.0f, hi = 0.0f;
    #pragma unroll 1
    for (int it = 0; it < 12; ++it) {
        float mid = 0.5f * (lo + hi);
        float s0 = 0.f, s1 = 0.f, s2 = 0.f, s3 = 0.f;
        #pragma unroll
        for (int k = 0; k < 64; k += 4) {
            float a0 = fmaxf(z[k + 0] - mid, 0.f); s0 = fmaf(a0, a0, s0);
            float a1 = fmaxf(z[k + 1] - mid, 0.f); s1 = fmaf(a1, a1, s1);
            float a2 = fmaxf(z[k + 2] - mid, 0.f); s2 = fmaf(a2, a2, s2);
            float a3 = fmaxf(z[k + 3] - mid, 0.f); s3 = fmaf(a3, a3, s3);
        }
        float s = (s0 + s1) + (s2 + s3);
        s += __shfl_xor_sync(0xffffffffu, s, 1);
        if (s >= 1.0f) lo = mid; else hi = mid;
    }
    float tau = 0.5f * (lo + hi);
    #pragma unroll 1
    for (int it = 0; it < 2; ++it) {
        float f0 = 0.f, f1 = 0.f, g0 = 0.f, g1 = 0.f;
        #pragma unroll
        for (int k = 0; k < 64; k += 2) {
            float a0 = fmaxf(z[k + 0] - tau, 0.f); f0 = fmaf(a0, a0, f0); g0 += a0;
            float a1 = fmaxf(z[k + 1] - tau, 0.f); f1 = fmaf(a1, a1, f1); g1 += a1;
        }
        float f = f0 + f1, g = g0 + g1;
        f += __shfl_xor_sync(0xffffffffu, f, 1);
        g += __shfl_xor_sync(0xffffffffu, g, 1);
        tau += (f - 1.0f) / fmaxf(2.0f * g, 1e-12f);
    }

    size_t base = ((size_t)mn * T_ + col) * D_ + half * 64;
    #pragma unroll
    for (int k = 0; k < 64; k += 2) {
        float a0 = fmaxf(z[k] - tau, 0.f);
        float a1 = fmaxf(z[k + 1] - tau, 0.f);
        unsigned h, l;
        split2(a0 * a0, a1 * a1, h, l);
        *(unsigned*)(g_wh + base + k) = h;
        *(unsigned*)(g_wl + base + k) = l;
    }
}

// ---------------------------------------------------------------------------
// K2: priors GEMM via mma.sync bf16, 3 hi/lo products, cp.async-pipelined.
//     One CTA per (m, b-chunk of 64): grid 256 (one full resident wave at
//     2 CTAs/SM). A = x[m][chunk] [64 b][128 d] hi/lo staged once; W^T[mn]
//     [64 t][128 d] hi/lo double-buffered via cp.async while mma runs.
//     8 warps: wm = w&3 (m16 group), wn = w>>2 (t half). 96 mma/warp/n.
//     smem: Ah 0 | Al 17408 | Wbuf0 34816 | Wbuf1 69632 -> 104448 B.
// ---------------------------------------------------------------------------
#define KP_SMEM 104448

__global__ __launch_bounds__(256) void k_priors_mma() {
    extern __shared__ __align__(16) char smc[];
    unsigned abase = (unsigned)__cvta_generic_to_shared(smc);
    int tid = threadIdx.x, lane = tid & 31, w = tid >> 5;
    int m = blockIdx.x >> 2, chunk = blockIdx.x & 3;

    // stage A: 64 b-rows x 128 d hi/lo, 272B rows (conflict-free for ldmatrix)
    {
        const uint4* sh = (const uint4*)(g_xh + ((size_t)m * B_ + chunk * 64) * D_);
        const uint4* sl = (const uint4*)(g_xl + ((size_t)m * B_ + chunk * 64) * D_);
        for (int i = tid; i < 1024; i += 256) {
            int r = i >> 4, q = i & 15;
            *(uint4*)(smc + r * 272 + q * 16) = sh[i];
            *(uint4*)(smc + 17408 + r * 272 + q * 16) = sl[i];
        }
    }

    // cp.async stage of W(n) into buffer buf
    auto stage_w = [&](int n, int buf) {
        unsigned dsth = abase + 34816u + (unsigned)buf * 34816u;
        unsigned dstl = dsth + 17408u;
        const char* srch = (const char*)(g_wh + (size_t)(m * 32 + n) * T_ * D_);
        const char* srcl = (const char*)(g_wl + (size_t)(m * 32 + n) * T_ * D_);
        for (int i = tid; i < 1024; i += 256) {
            int r = i >> 4, q = i & 15;
            unsigned off = (unsigned)(r * 272 + q * 16);
            asm volatile("cp.async.cg.shared.global [%0], [%1], 16;"
                         :: "r"(dsth + off), "l"(srch + (size_t)i * 16) : "memory");
            asm volatile("cp.async.cg.shared.global [%0], [%1], 16;"
                         :: "r"(dstl + off), "l"(srcl + (size_t)i * 16) : "memory");
        }
        asm volatile("cp.async.commit_group;" ::: "memory");
    };
    stage_w(0, 0);

    int wm = w & 3, wn = w >> 2;
    unsigned a_off = (unsigned)((wm * 16 + (lane & 15)) * 272) + ((lane & 16) ? 16u : 0u);
    unsigned Ah_b = abase + a_off;
    unsigned Al_b = Ah_b + 17408u;
    unsigned b_row = (unsigned)((lane & 7) + ((lane & 16) ? 8 : 0));
    unsigned b_col = (lane & 8) ? 16u : 0u;
    unsigned w_off = (unsigned)(wn * 32 + (int)b_row) * 272u + b_col;

    #pragma unroll 1
    for (int n = 0; n < 32; ++n) {
        if (n < 31) {
            stage_w(n + 1, (n + 1) & 1);
            asm volatile("cp.async.wait_group 1;" ::: "memory");
        } else {
            asm volatile("cp.async.wait_group 0;" ::: "memory");
        }
        __syncthreads();  // W(n) visible; also orders A stage on first iter

        unsigned Wh_b = abase + 34816u + (unsigned)(n & 1) * 34816u + w_off;
        unsigned Wl_b = Wh_b + 17408u;

        float acc[4][4];
        #pragma unroll
        for (int j8 = 0; j8 < 4; ++j8)
            #pragma unroll
            for (int q = 0; q < 4; ++q) acc[j8][q] = 0.f;

        #pragma unroll 1
        for (int ks = 0; ks < 8; ++ks) {
            unsigned ra_h[4], ra_l[4];
            asm volatile("ldmatrix.sync.aligned.m8n8.x4.shared.b16 {%0,%1,%2,%3},[%4];"
                         : "=r"(ra_h[0]), "=r"(ra_h[1]), "=r"(ra_h[2]), "=r"(ra_h[3])
                         : "r"(Ah_b + (unsigned)ks * 32u));
            asm volatile("ldmatrix.sync.aligned.m8n8.x4.shared.b16 {%0,%1,%2,%3},[%4];"
                         : "=r"(ra_l[0]), "=r"(ra_l[1]), "=r"(ra_l[2]), "=r"(ra_l[3])
                         : "r"(Al_b + (unsigned)ks * 32u));
            #pragma unroll
            for (int j = 0; j < 2; ++j) {  // n16 groups within this warp's t-half
                unsigned rb_h[4], rb_l[4];
                unsigned boff = (unsigned)j * 4352u + (unsigned)ks * 32u;  // 16*272
                asm volatile("ldmatrix.sync.aligned.m8n8.x4.shared.b16 {%0,%1,%2,%3},[%4];"
                             : "=r"(rb_h[0]), "=r"(rb_h[1]), "=r"(rb_h[2]), "=r"(rb_h[3])
                             : "r"(Wh_b + boff));
                asm volatile("ldmatrix.sync.aligned.m8n8.x4.shared.b16 {%0,%1,%2,%3},[%4];"
                             : "=r"(rb_l[0]), "=r"(rb_l[1]), "=r"(rb_l[2]), "=r"(rb_l[3])
                             : "r"(Wl_b + boff));
                #pragma unroll
                for (int h = 0; h < 2; ++h) {
                    float* A0 = acc[2 * j + h];
                    asm volatile(
                        "mma.sync.aligned.m16n8k16.row.col.f32.bf16.bf16.f32 "
                        "{%0,%1,%2,%3},{%4,%5,%6,%7},{%8,%9},{%0,%1,%2,%3};"
                        : "+f"(A0[0]), "+f"(A0[1]), "+f"(A0[2]), "+f"(A0[3])
                        : "r"(ra_h[0]), "r"(ra_h[1]), "r"(ra_h[2]), "r"(ra_h[3]),
                          "r"(rb_h[2 * h]), "r"(rb_h[2 * h + 1]));
                    asm volatile(
                        "mma.sync.aligned.m16n8k16.row.col.f32.bf16.bf16.f32 "
                        "{%0,%1,%2,%3},{%4,%5,%6,%7},{%8,%9},{%0,%1,%2,%3};"
                        : "+f"(A0[0]), "+f"(A0[1]), "+f"(A0[2]), "+f"(A0[3])
                        : "r"(ra_h[0]), "r"(ra_h[1]), "r"(ra_h[2]), "r"(ra_h[3]),
                          "r"(rb_l[2 * h]), "r"(rb_l[2 * h + 1]));
                    asm volatile(
                        "mma.sync.aligned.m16n8k16.row.col.f32.bf16.bf16.f32 "
                        "{%0,%1,%2,%3},{%4,%5,%6,%7},{%8,%9},{%0,%1,%2,%3};"
                        : "+f"(A0[0]), "+f"(A0[1]), "+f"(A0[2]), "+f"(A0[3])
                        : "r"(ra_l[0]), "r"(ra_l[1]), "r"(ra_l[2]), "r"(ra_l[3]),
                          "r"(rb_h[2 * h]), "r"(rb_h[2 * h + 1]));
                }
            }
        }

        // epilogue: split & store priors hi/lo [n][b][m][t]
        {
            int b = chunk * 64 + wm * 16 + (lane >> 2);
            size_t pb = (((size_t)n * B_ + b) * M_ + m) * T_;
            #pragma unroll
            for (int j8 = 0; j8 < 4; ++j8) {
                int t = wn * 32 + j8 * 8 + (lane & 3) * 2;
                unsigned h0, l0, h1, l1;
                split2(acc[j8][0], acc[j8][1], h0, l0);
                split2(acc[j8][2], acc[j8][3], h1, l1);
                *(unsigned*)(g_ph + pb + t) = h0;
                *(unsigned*)(g_pl + pb + t) = l0;
                *(unsigned*)(g_ph + pb + 8 * (size_t)(M_ * T_) + t) = h1;  // b+8
                *(unsigned*)(g_pl + pb + 8 * (size_t)(M_ * T_) + t) = l1;
            }
        }
        __syncthreads();  // mma reads of buf[n&1] done before it is re-filled
    }
}

// ---------------------------------------------------------------------------
// K3: votes GEMM via mma.sync (unchanged, validated at 189us).
// ---------------------------------------------------------------------------
#define K3_SMEM 80384

__global__ __launch_bounds__(256) void k_route(
    const float* __restrict__ thr, const float* __restrict__ gamma,
    const float* __restrict__ beta, float* __restrict__ out)
{
    extern __shared__ __align__(16) char smc[];
    unsigned abase = (unsigned)__cvta_generic_to_shared(smc);

    float* table = (float*)(smc + 73728);   // [8 warps][128 l]
    float* vbar  = (float*)(smc + 77824);   // [2][128]
    float* wgt   = (float*)(smc + 78848);   // [128]
    float* prob  = (float*)(smc + 79360);   // [128]
    float* ncs   = (float*)(smc + 79872);   // [128]

    int tid = threadIdx.x;
    int lane = tid & 31, w = tid >> 5;
    int n = blockIdx.x >> 7, bp = blockIdx.x & 127;

    {
        size_t pbase = (((size_t)n * B_ + 2 * bp) * M_) * T_;
        const uint4* sh = (const uint4*)(g_ph + pbase);
        const uint4* sl = (const uint4*)(g_pl + pbase);
        for (int i = tid; i < 1024; i += 256) {
            int r = i >> 3, q = i & 7;
            *(uint4*)(smc + r * 144 + q * 16) = sh[i];
            *(uint4*)(smc + 18432 + r * 144 + q * 16) = sl[i];
        }
        const uint4* th = (const uint4*)g_lhh;
        const uint4* tl = (const uint4*)g_lhl;
        for (int i = tid; i < 1024; i += 256) {
            int r = i >> 3, q = i & 7;
            *(uint4*)(smc + 36864 + r * 144 + q * 16) = th[i];
            *(uint4*)(smc + 55296 + r * 144 + q * 16) = tl[i];
        }
    }
    __syncthreads();

    int m0 = w * 16;
    unsigned a_off = (unsigned)((m0 + (lane & 15)) * 144) + ((lane & 16) ? 16u : 0u);
    unsigned Ah_b = abase + a_off;
    unsigned Al_b = abase + 18432u + a_off;
    unsigned b_row = (unsigned)((lane & 7) + ((lane & 16) ? 8 : 0));
    unsigned b_col = (lane & 8) ? 16u : 0u;
    unsigned Bh_b = abase + 36864u + b_row * 144u + b_col;
    unsigned Bl_b = Bh_b + 18432u;

    float acc[16][4];
    #pragma unroll
    for (int nt = 0; nt < 16; ++nt)
        #pragma unroll
        for (int q = 0; q < 4; ++q) acc[nt][q] = 0.f;

    #pragma unroll 1
    for (int ks = 0; ks < 4; ++ks) {
        unsigned ra_h[4], ra_l[4];
        asm volatile("ldmatrix.sync.aligned.m8n8.x4.shared.b16 {%0,%1,%2,%3},[%4];"
                     : "=r"(ra_h[0]), "=r"(ra_h[1]), "=r"(ra_h[2]), "=r"(ra_h[3])
                     : "r"(Ah_b + (unsigned)ks * 32u));
        asm volatile("ldmatrix.sync.aligned.m8n8.x4.shared.b16 {%0,%1,%2,%3},[%4];"
                     : "=r"(ra_l[0]), "=r"(ra_l[1]), "=r"(ra_l[2]), "=r"(ra_l[3])
                     : "r"(Al_b + (unsigned)ks * 32u));
        #pragma unroll
        for (int np = 0; np < 8; ++np) {
            unsigned rb_h[4], rb_l[4];
            unsigned boff = (unsigned)np * 2304u + (unsigned)ks * 32u;
            asm volatile("ldmatrix.sync.aligned.m8n8.x4.shared.b16 {%0,%1,%2,%3},[%4];"
                         : "=r"(rb_h[0]), "=r"(rb_h[1]), "=r"(rb_h[2]), "=r"(rb_h[3])
                         : "r"(Bh_b + boff));
            asm volatile("ldmatrix.sync.aligned.m8n8.x4.shared.b16 {%0,%1,%2,%3},[%4];"
                         : "=r"(rb_l[0]), "=r"(rb_l[1]), "=r"(rb_l[2]), "=r"(rb_l[3])
                         : "r"(Bl_b + boff));
            #pragma unroll
            for (int h = 0; h < 2; ++h) {
                float* A0 = acc[2 * np + h];
                asm volatile(
                    "mma.sync.aligned.m16n8k16.row.col.f32.bf16.bf16.f32 "
                    "{%0,%1,%2,%3},{%4,%5,%6,%7},{%8,%9},{%0,%1,%2,%3};"
                    : "+f"(A0[0]), "+f"(A0[1]), "+f"(A0[2]), "+f"(A0[3])
                    : "r"(ra_h[0]), "r"(ra_h[1]), "r"(ra_h[2]), "r"(ra_h[3]),
                      "r"(rb_h[2 * h]), "r"(rb_h[2 * h + 1]));
                asm volatile(
                    "mma.sync.aligned.m16n8k16.row.col.f32.bf16.bf16.f32 "
                    "{%0,%1,%2,%3},{%4,%5,%6,%7},{%8,%9},{%0,%1,%2,%3};"
                    : "+f"(A0[0]), "+f"(A0[1]), "+f"(A0[2]), "+f"(A0[3])
                    : "r"(ra_h[0]), "r"(ra_h[1]), "r"(ra_h[2]), "r"(ra_h[3]),
                      "r"(rb_l[2 * h]), "r"(rb_l[2 * h + 1]));
                asm volatile(
                    "mma.sync.aligned.m16n8k16.row.col.f32.bf16.bf16.f32 "
                    "{%0,%1,%2,%3},{%4,%5,%6,%7},{%8,%9},{%0,%1,%2,%3};"
                    : "+f"(A0[0]), "+f"(A0[1]), "+f"(A0[2]), "+f"(A0[3])
                    : "r"(ra_l[0]), "r"(ra_l[1]), "r"(ra_l[2]), "r"(ra_l[3]),
                      "r"(rb_h[2 * h]), "r"(rb_h[2 * h + 1]));
            }
        }
    }

    #pragma unroll
    for (int nt = 0; nt < 16; ++nt)
        #pragma unroll
        for (int q = 0; q < 4; ++q)
            acc[nt][q] = 1.0f / (1.0f + __expf(-acc[nt][q]));

    {
        float cs0[16], cs1[16];
        #pragma unroll
        for (int nt = 0; nt < 16; ++nt) {
            cs0[nt] = acc[nt][0] + acc[nt][2];
            cs1[nt] = acc[nt][1] + acc[nt][3];
        }
        #pragma unroll
        for (int s = 4; s <= 16; s <<= 1)
            #pragma unroll
            for (int nt = 0; nt < 16; ++nt) {
                cs0[nt] += __shfl_xor_sync(0xffffffffu, cs0[nt], s);
                cs1[nt] += __shfl_xor_sync(0xffffffffu, cs1[nt], s);
            }
        if (lane < 4) {
            #pragma unroll
            for (int nt = 0; nt < 16; ++nt)
                *(float2*)(table + w * 128 + nt * 8 + lane * 2) = make_float2(cs0[nt], cs1[nt]);
        }
    }
    __syncthreads();

    {
        int bb = tid >> 7, l = tid & 127;
        float s = table[(bb * 4 + 0) * 128 + l] + table[(bb * 4 + 1) * 128 + l]
                + table[(bb * 4 + 2) * 128 + l] + table[(bb * 4 + 3) * 128 + l];
        vbar[bb * 128 + l] = s * (1.0f / 64.0f);
    }
    __syncthreads();

    {
        int bb = w >> 2;
        float dis0 = 0.f, dis1 = 0.f;
        #pragma unroll
        for (int nt = 0; nt < 16; ++nt) {
            int c = nt * 8 + (lane & 3) * 2;
            float2 vb = *(const float2*)(vbar + bb * 128 + c);
            float d;
            d = acc[nt][0] - vb.x; dis0 = fmaf(d, d, dis0);
            d = acc[nt][1] - vb.y; dis0 = fmaf(d, d, dis0);
            d = acc[nt][2] - vb.x; dis1 = fmaf(d, d, dis1);
            d = acc[nt][3] - vb.y; dis1 = fmaf(d, d, dis1);
        }
        dis0 += __shfl_xor_sync(0xffffffffu, dis0, 1);
        dis0 += __shfl_xor_sync(0xffffffffu, dis0, 2);
        dis1 += __shfl_xor_sync(0xffffffffu, dis1, 1);
        dis1 += __shfl_xor_sync(0xffffffffu, dis1, 2);
        if ((lane & 3) == 0) {
            int row0 = m0 + (lane >> 2);
            float tw0 = thr[(row0 & 63) * N_ + n];
            float tw1 = thr[((row0 + 8) & 63) * N_ + n];
            wgt[row0]     = fmaxf(fmaf(tw0, tw0, -dis0 * (1.0f / L_)), 0.0f);
            wgt[row0 + 8] = fmaxf(fmaf(tw1, tw1, -dis1 * (1.0f / L_)), 0.0f);
        }
    }
    __syncthreads();

    if (tid < 128) {
        int bb = tid >> 6;
        float mxw = -3.0e38f;
        #pragma unroll 8
        for (int mm = 0; mm < 64; ++mm) mxw = fmaxf(mxw, wgt[bb * 64 + mm]);
        prob[tid] = __expf(wgt[tid] - mxw);
    }
    __syncthreads();

    if (tid < 128) {
        int bb = tid >> 6, t = tid & 63;
        const __nv_bfloat16* Ah = (const __nv_bfloat16*)smc;
        const __nv_bfloat16* Al = (const __nv_bfloat16*)(smc + 18432);
        float psum = 0.f;
        #pragma unroll 8
        for (int mm = 0; mm < 64; ++mm) psum += prob[bb * 64 + mm];
        float nc = 0.f;
        #pragma unroll 4
        for (int mm = 0; mm < 64; ++mm) {
            int row = bb * 64 + mm;
            float p = __bfloat162float(Ah[row * 72 + t]) + __bfloat162float(Al[row * 72 + t]);
            nc = fmaf(prob[bb * 64 + mm], p, nc);
        }
        ncs[tid] = nc / psum;
    }
    __syncthreads();

    if (tid < 128) {
        int bb = tid >> 6, t = tid & 63;
        float mu = 0.f;
        #pragma unroll 8
        for (int t2 = 0; t2 < T_; ++t2) mu += ncs[bb * 64 + t2];
        mu *= (1.0f / T_);
        float var = 0.f;
        #pragma unroll 8
        for (int t2 = 0; t2 < T_; ++t2) {
            float dv = ncs[bb * 64 + t2] - mu;
            var = fmaf(dv, dv, var);
        }
        var *= (1.0f / T_);
        float y = (ncs[tid] - mu) * rsqrtf(var + 1e-5f) * gamma[t] + beta[t];
        out[((size_t)(2 * bp + bb) * N_ + n) * T_ + t] = y;
    }
}

// ---------------------------------------------------------------------------
// Launch
// ---------------------------------------------------------------------------
extern "C" void kernel_launch(void* const* d_in, const int* in_sizes, int n_in,
                              void* d_out, int out_size) {
    const float* x      = (const float*)d_in[0];
    const float* rw     = (const float*)d_in[1];
    const float* thr    = (const float*)d_in[2];
    const float* leaves = (const float*)d_in[3];
    const float* gamma  = (const float*)d_in[4];
    const float* beta   = (const float*)d_in[5];
    float* out = (float*)d_out;

    static int attr_set = 0;
    if (!attr_set) {
        cudaFuncSetAttribute(k_priors_mma, cudaFuncAttributeMaxDynamicSharedMemorySize, KP_SMEM);
        cudaFuncSetAttribute(k_route, cudaFuncAttributeMaxDynamicSharedMemorySize, K3_SMEM);
        attr_set = 1;
    }

    k_leaves<<<1, 128>>>(leaves);
    k_xsplit<<<M_, 256>>>(x);
    k_entmax<<<M_ * N_, 128>>>(rw);
    k_priors_mma<<<M_ * 4, 256, KP_SMEM>>>();
    k_route<<<N_ * 128, 256, K3_SMEM>>>(thr, gamma, beta, out);
}

// round 17
// speedup vs baseline: 1.3912x; 1.1765x over previous
#include <cuda_runtime.h>
#include <cuda_bf16.h>
#include <cstdint>
#include <math.h>

#define B_ 256
#define M_ 64
#define N_ 32
#define D_ 128
#define T_ 64
#define L_ 128

// Scratch (allocation-free: __device__ globals)
__device__ __nv_bfloat16 g_xh[(size_t)M_ * B_ * D_];       // x hi, [m][b][d]
__device__ __nv_bfloat16 g_xl[(size_t)M_ * B_ * D_];       // x lo
__device__ __nv_bfloat16 g_wh[(size_t)M_ * N_ * T_ * D_];  // entmax W^T hi, [mn][t][d]
__device__ __nv_bfloat16 g_wl[(size_t)M_ * N_ * T_ * D_];  // entmax W^T lo
__device__ __nv_bfloat16 g_ph[(size_t)N_ * B_ * M_ * T_];  // priors hi, [n][b][m][t]
__device__ __nv_bfloat16 g_pl[(size_t)N_ * B_ * M_ * T_];  // priors lo
__device__ __nv_bfloat16 g_lhh[L_ * T_];                   // leaves hi, [l][t]
__device__ __nv_bfloat16 g_lhl[L_ * T_];                   // leaves lo

// pack (a,b) into bf16x2 hi word + bf16x2 lo-residual word
__device__ __forceinline__ void split2(float a, float b, unsigned& hi, unsigned& lo) {
    __nv_bfloat16 ha = __float2bfloat16(a), hb = __float2bfloat16(b);
    __nv_bfloat16 la = __float2bfloat16(a - __bfloat162float(ha));
    __nv_bfloat16 lb = __float2bfloat16(b - __bfloat162float(hb));
    hi = (unsigned)__bfloat16_as_ushort(ha) | ((unsigned)__bfloat16_as_ushort(hb) << 16);
    lo = (unsigned)__bfloat16_as_ushort(la) | ((unsigned)__bfloat16_as_ushort(lb) << 16);
}

// ---------------------------------------------------------------------------
// K0a: normalize routing_leaves rows; emit bf16 hi/lo [l][t]
// ---------------------------------------------------------------------------
__global__ void k_leaves(const float* __restrict__ leaves) {
    int l = threadIdx.x;
    if (l >= L_) return;
    float v[T_];
    float s = 0.f;
    #pragma unroll
    for (int t = 0; t < T_; ++t) { v[t] = leaves[l * T_ + t]; s = fmaf(v[t], v[t], s); }
    float inv = 1.0f / fmaxf(sqrtf(s), 1e-12f);
    #pragma unroll
    for (int t = 0; t < T_; ++t) {
        float f = v[t] * inv;
        __nv_bfloat16 h = __float2bfloat16(f);
        g_lhh[l * T_ + t] = h;
        g_lhl[l * T_ + t] = __float2bfloat16(f - __bfloat162float(h));
    }
}

// ---------------------------------------------------------------------------
// K0b: split x into bf16 hi/lo, transposed to [m][b][d]
// ---------------------------------------------------------------------------
__global__ __launch_bounds__(256) void k_xsplit(const float* __restrict__ x) {
    int m = blockIdx.x;
    for (int i = threadIdx.x; i < B_ * D_; i += 256) {
        int b = i >> 7, d = i & 127;
        float f = x[((size_t)b * M_ + m) * D_ + d];
        __nv_bfloat16 h = __float2bfloat16(f);
        size_t o = ((size_t)m * B_ + b) * D_ + d;
        g_xh[o] = h;
        g_xl[o] = __float2bfloat16(f - __bfloat162float(h));
    }
}

// ---------------------------------------------------------------------------
// K1: exact 1.5-entmax over D per (m,n,t) column via 12 bisection + 2 Newton.
//     2 threads/column. Weights staged to smem [t][d] (stride 130, reusing
//     the load buffer), then streamed out as coalesced bf16 hi/lo words.
// ---------------------------------------------------------------------------
__global__ __launch_bounds__(128) void k_entmax(const float* __restrict__ rw) {
    __shared__ float sm[D_ * 65];  // 8320 floats; reused as wbuf [64 t][130]
    int mn = blockIdx.x;
    const float* src = rw + (size_t)mn * D_ * T_;
    for (int i = threadIdx.x; i < D_ * T_; i += 128)
        sm[(i >> 6) * 65 + (i & 63)] = src[i];
    __syncthreads();

    int col = threadIdx.x >> 1, half = threadIdx.x & 1;
    float z[64];
    float mx = -3.0e38f;
    #pragma unroll
    for (int k = 0; k < 64; ++k) {
        z[k] = sm[(half * 64 + k) * 65 + col];
        mx = fmaxf(mx, z[k]);
    }
    mx = fmaxf(mx, __shfl_xor_sync(0xffffffffu, mx, 1));
    #pragma unroll
    for (int k = 0; k < 64; ++k) z[k] = 0.5f * z[k] - 0.5f * mx;

    float lo = -1.0f, hi = 0.0f;
    #pragma unroll 1
    for (int it = 0; it < 12; ++it) {
        float mid = 0.5f * (lo + hi);
        float s0 = 0.f, s1 = 0.f, s2 = 0.f, s3 = 0.f;
        #pragma unroll
        for (int k = 0; k < 64; k += 4) {
            float a0 = fmaxf(z[k + 0] - mid, 0.f); s0 = fmaf(a0, a0, s0);
            float a1 = fmaxf(z[k + 1] - mid, 0.f); s1 = fmaf(a1, a1, s1);
            float a2 = fmaxf(z[k + 2] - mid, 0.f); s2 = fmaf(a2, a2, s2);
            float a3 = fmaxf(z[k + 3] - mid, 0.f); s3 = fmaf(a3, a3, s3);
        }
        float s = (s0 + s1) + (s2 + s3);
        s += __shfl_xor_sync(0xffffffffu, s, 1);
        if (s >= 1.0f) lo = mid; else hi = mid;
    }
    float tau = 0.5f * (lo + hi);
    #pragma unroll 1
    for (int it = 0; it < 2; ++it) {
        float f0 = 0.f, f1 = 0.f, g0 = 0.f, g1 = 0.f;
        #pragma unroll
        for (int k = 0; k < 64; k += 2) {
            float a0 = fmaxf(z[k + 0] - tau, 0.f); f0 = fmaf(a0, a0, f0); g0 += a0;
            float a1 = fmaxf(z[k + 1] - tau, 0.f); f1 = fmaf(a1, a1, f1); g1 += a1;
        }
        float f = f0 + f1, g = g0 + g1;
        f += __shfl_xor_sync(0xffffffffu, f, 1);
        g += __shfl_xor_sync(0xffffffffu, g, 1);
        tau += (f - 1.0f) / fmaxf(2.0f * g, 1e-12f);
    }

    __syncthreads();  // all initial sm reads done -> safe to overwrite as wbuf
    // wbuf[t][d] = weight, t = col, d = half*64 + k (stride 130 floats)
    #pragma unroll
    for (int k = 0; k < 64; ++k) {
        float a = fmaxf(z[k] - tau, 0.f);
        sm[col * 130 + half * 64 + k] = a * a;
    }
    __syncthreads();

    // coalesced output: word j -> t = j >> 6, dpair = j & 63
    size_t base = (size_t)mn * T_ * D_;
    for (int j = threadIdx.x; j < T_ * D_ / 2; j += 128) {
        int t = j >> 6, dp = j & 63;
        float a0 = sm[t * 130 + 2 * dp];
        float a1 = sm[t * 130 + 2 * dp + 1];
        unsigned h, l;
        split2(a0, a1, h, l);
        *(unsigned*)(g_wh + base + 2 * (size_t)j) = h;
        *(unsigned*)(g_wl + base + 2 * (size_t)j) = l;
    }
}

// ---------------------------------------------------------------------------
// K2: priors GEMM via mma.sync bf16, 3 hi/lo products, cp.async-pipelined.
//     One CTA per (m, b-chunk of 64): grid 256. A staged once; W^T double-
//     buffered via cp.async. (unchanged from R16, validated 117.7us)
// ---------------------------------------------------------------------------
#define KP_SMEM 104448

__global__ __launch_bounds__(256) void k_priors_mma() {
    extern __shared__ __align__(16) char smc[];
    unsigned abase = (unsigned)__cvta_generic_to_shared(smc);
    int tid = threadIdx.x, lane = tid & 31, w = tid >> 5;
    int m = blockIdx.x >> 2, chunk = blockIdx.x & 3;

    {
        const uint4* sh = (const uint4*)(g_xh + ((size_t)m * B_ + chunk * 64) * D_);
        const uint4* sl = (const uint4*)(g_xl + ((size_t)m * B_ + chunk * 64) * D_);
        for (int i = tid; i < 1024; i += 256) {
            int r = i >> 4, q = i & 15;
            *(uint4*)(smc + r * 272 + q * 16) = sh[i];
            *(uint4*)(smc + 17408 + r * 272 + q * 16) = sl[i];
        }
    }

    auto stage_w = [&](int n, int buf) {
        unsigned dsth = abase + 34816u + (unsigned)buf * 34816u;
        unsigned dstl = dsth + 17408u;
        const char* srch = (const char*)(g_wh + (size_t)(m * 32 + n) * T_ * D_);
        const char* srcl = (const char*)(g_wl + (size_t)(m * 32 + n) * T_ * D_);
        for (int i = tid; i < 1024; i += 256) {
            int r = i >> 4, q = i & 15;
            unsigned off = (unsigned)(r * 272 + q * 16);
            asm volatile("cp.async.cg.shared.global [%0], [%1], 16;"
                         :: "r"(dsth + off), "l"(srch + (size_t)i * 16) : "memory");
            asm volatile("cp.async.cg.shared.global [%0], [%1], 16;"
                         :: "r"(dstl + off), "l"(srcl + (size_t)i * 16) : "memory");
        }
        asm volatile("cp.async.commit_group;" ::: "memory");
    };
    stage_w(0, 0);

    int wm = w & 3, wn = w >> 2;
    unsigned a_off = (unsigned)((wm * 16 + (lane & 15)) * 272) + ((lane & 16) ? 16u : 0u);
    unsigned Ah_b = abase + a_off;
    unsigned Al_b = Ah_b + 17408u;
    unsigned b_row = (unsigned)((lane & 7) + ((lane & 16) ? 8 : 0));
    unsigned b_col = (lane & 8) ? 16u : 0u;
    unsigned w_off = (unsigned)(wn * 32 + (int)b_row) * 272u + b_col;

    #pragma unroll 1
    for (int n = 0; n < 32; ++n) {
        if (n < 31) {
            stage_w(n + 1, (n + 1) & 1);
            asm volatile("cp.async.wait_group 1;" ::: "memory");
        } else {
            asm volatile("cp.async.wait_group 0;" ::: "memory");
        }
        __syncthreads();

        unsigned Wh_b = abase + 34816u + (unsigned)(n & 1) * 34816u + w_off;
        unsigned Wl_b = Wh_b + 17408u;

        float acc[4][4];
        #pragma unroll
        for (int j8 = 0; j8 < 4; ++j8)
            #pragma unroll
            for (int q = 0; q < 4; ++q) acc[j8][q] = 0.f;

        #pragma unroll 1
        for (int ks = 0; ks < 8; ++ks) {
            unsigned ra_h[4], ra_l[4];
            asm volatile("ldmatrix.sync.aligned.m8n8.x4.shared.b16 {%0,%1,%2,%3},[%4];"
                         : "=r"(ra_h[0]), "=r"(ra_h[1]), "=r"(ra_h[2]), "=r"(ra_h[3])
                         : "r"(Ah_b + (unsigned)ks * 32u));
            asm volatile("ldmatrix.sync.aligned.m8n8.x4.shared.b16 {%0,%1,%2,%3},[%4];"
                         : "=r"(ra_l[0]), "=r"(ra_l[1]), "=r"(ra_l[2]), "=r"(ra_l[3])
                         : "r"(Al_b + (unsigned)ks * 32u));
            #pragma unroll
            for (int j = 0; j < 2; ++j) {
                unsigned rb_h[4], rb_l[4];
                unsigned boff = (unsigned)j * 4352u + (unsigned)ks * 32u;
                asm volatile("ldmatrix.sync.aligned.m8n8.x4.shared.b16 {%0,%1,%2,%3},[%4];"
                             : "=r"(rb_h[0]), "=r"(rb_h[1]), "=r"(rb_h[2]), "=r"(rb_h[3])
                             : "r"(Wh_b + boff));
                asm volatile("ldmatrix.sync.aligned.m8n8.x4.shared.b16 {%0,%1,%2,%3},[%4];"
                             : "=r"(rb_l[0]), "=r"(rb_l[1]), "=r"(rb_l[2]), "=r"(rb_l[3])
                             : "r"(Wl_b + boff));
                #pragma unroll
                for (int h = 0; h < 2; ++h) {
                    float* A0 = acc[2 * j + h];
                    asm volatile(
                        "mma.sync.aligned.m16n8k16.row.col.f32.bf16.bf16.f32 "
                        "{%0,%1,%2,%3},{%4,%5,%6,%7},{%8,%9},{%0,%1,%2,%3};"
                        : "+f"(A0[0]), "+f"(A0[1]), "+f"(A0[2]), "+f"(A0[3])
                        : "r"(ra_h[0]), "r"(ra_h[1]), "r"(ra_h[2]), "r"(ra_h[3]),
                          "r"(rb_h[2 * h]), "r"(rb_h[2 * h + 1]));
                    asm volatile(
                        "mma.sync.aligned.m16n8k16.row.col.f32.bf16.bf16.f32 "
                        "{%0,%1,%2,%3},{%4,%5,%6,%7},{%8,%9},{%0,%1,%2,%3};"
                        : "+f"(A0[0]), "+f"(A0[1]), "+f"(A0[2]), "+f"(A0[3])
                        : "r"(ra_h[0]), "r"(ra_h[1]), "r"(ra_h[2]), "r"(ra_h[3]),
                          "r"(rb_l[2 * h]), "r"(rb_l[2 * h + 1]));
                    asm volatile(
                        "mma.sync.aligned.m16n8k16.row.col.f32.bf16.bf16.f32 "
                        "{%0,%1,%2,%3},{%4,%5,%6,%7},{%8,%9},{%0,%1,%2,%3};"
                        : "+f"(A0[0]), "+f"(A0[1]), "+f"(A0[2]), "+f"(A0[3])
                        : "r"(ra_l[0]), "r"(ra_l[1]), "r"(ra_l[2]), "r"(ra_l[3]),
                          "r"(rb_h[2 * h]), "r"(rb_h[2 * h + 1]));
                }
            }
        }

        {
            int b = chunk * 64 + wm * 16 + (lane >> 2);
            size_t pb = (((size_t)n * B_ + b) * M_ + m) * T_;
            #pragma unroll
            for (int j8 = 0; j8 < 4; ++j8) {
                int t = wn * 32 + j8 * 8 + (lane & 3) * 2;
                unsigned h0, l0, h1, l1;
                split2(acc[j8][0], acc[j8][1], h0, l0);
                split2(acc[j8][2], acc[j8][3], h1, l1);
                *(unsigned*)(g_ph + pb + t) = h0;
                *(unsigned*)(g_pl + pb + t) = l0;
                *(unsigned*)(g_ph + pb + 8 * (size_t)(M_ * T_) + t) = h1;
                *(unsigned*)(g_pl + pb + 8 * (size_t)(M_ * T_) + t) = l1;
            }
        }
        __syncthreads();
    }
}

// ---------------------------------------------------------------------------
// K3: votes GEMM via mma.sync (unchanged, validated at 189us).
// ---------------------------------------------------------------------------
#define K3_SMEM 80384

__global__ __launch_bounds__(256) void k_route(
    const float* __restrict__ thr, const float* __restrict__ gamma,
    const float* __restrict__ beta, float* __restrict__ out)
{
    extern __shared__ __align__(16) char smc[];
    unsigned abase = (unsigned)__cvta_generic_to_shared(smc);

    float* table = (float*)(smc + 73728);   // [8 warps][128 l]
    float* vbar  = (float*)(smc + 77824);   // [2][128]
    float* wgt   = (float*)(smc + 78848);   // [128]
    float* prob  = (float*)(smc + 79360);   // [128]
    float* ncs   = (float*)(smc + 79872);   // [128]

    int tid = threadIdx.x;
    int lane = tid & 31, w = tid >> 5;
    int n = blockIdx.x >> 7, bp = blockIdx.x & 127;

    {
        size_t pbase = (((size_t)n * B_ + 2 * bp) * M_) * T_;
        const uint4* sh = (const uint4*)(g_ph + pbase);
        const uint4* sl = (const uint4*)(g_pl + pbase);
        for (int i = tid; i < 1024; i += 256) {
            int r = i >> 3, q = i & 7;
            *(uint4*)(smc + r * 144 + q * 16) = sh[i];
            *(uint4*)(smc + 18432 + r * 144 + q * 16) = sl[i];
        }
        const uint4* th = (const uint4*)g_lhh;
        const uint4* tl = (const uint4*)g_lhl;
        for (int i = tid; i < 1024; i += 256) {
            int r = i >> 3, q = i & 7;
            *(uint4*)(smc + 36864 + r * 144 + q * 16) = th[i];
            *(uint4*)(smc + 55296 + r * 144 + q * 16) = tl[i];
        }
    }
    __syncthreads();

    int m0 = w * 16;
    unsigned a_off = (unsigned)((m0 + (lane & 15)) * 144) + ((lane & 16) ? 16u : 0u);
    unsigned Ah_b = abase + a_off;
    unsigned Al_b = abase + 18432u + a_off;
    unsigned b_row = (unsigned)((lane & 7) + ((lane & 16) ? 8 : 0));
    unsigned b_col = (lane & 8) ? 16u : 0u;
    unsigned Bh_b = abase + 36864u + b_row * 144u + b_col;
    unsigned Bl_b = Bh_b + 18432u;

    float acc[16][4];
    #pragma unroll
    for (int nt = 0; nt < 16; ++nt)
        #pragma unroll
        for (int q = 0; q < 4; ++q) acc[nt][q] = 0.f;

    #pragma unroll 1
    for (int ks = 0; ks < 4; ++ks) {
        unsigned ra_h[4], ra_l[4];
        asm volatile("ldmatrix.sync.aligned.m8n8.x4.shared.b16 {%0,%1,%2,%3},[%4];"
                     : "=r"(ra_h[0]), "=r"(ra_h[1]), "=r"(ra_h[2]), "=r"(ra_h[3])
                     : "r"(Ah_b + (unsigned)ks * 32u));
        asm volatile("ldmatrix.sync.aligned.m8n8.x4.shared.b16 {%0,%1,%2,%3},[%4];"
                     : "=r"(ra_l[0]), "=r"(ra_l[1]), "=r"(ra_l[2]), "=r"(ra_l[3])
                     : "r"(Al_b + (unsigned)ks * 32u));
        #pragma unroll
        for (int np = 0; np < 8; ++np) {
            unsigned rb_h[4], rb_l[4];
            unsigned boff = (unsigned)np * 2304u + (unsigned)ks * 32u;
            asm volatile("ldmatrix.sync.aligned.m8n8.x4.shared.b16 {%0,%1,%2,%3},[%4];"
                         : "=r"(rb_h[0]), "=r"(rb_h[1]), "=r"(rb_h[2]), "=r"(rb_h[3])
                         : "r"(Bh_b + boff));
            asm volatile("ldmatrix.sync.aligned.m8n8.x4.shared.b16 {%0,%1,%2,%3},[%4];"
                         : "=r"(rb_l[0]), "=r"(rb_l[1]), "=r"(rb_l[2]), "=r"(rb_l[3])
                         : "r"(Bl_b + boff));
            #pragma unroll
            for (int h = 0; h < 2; ++h) {
                float* A0 = acc[2 * np + h];
                asm volatile(
                    "mma.sync.aligned.m16n8k16.row.col.f32.bf16.bf16.f32 "
                    "{%0,%1,%2,%3},{%4,%5,%6,%7},{%8,%9},{%0,%1,%2,%3};"
                    : "+f"(A0[0]), "+f"(A0[1]), "+f"(A0[2]), "+f"(A0[3])
                    : "r"(ra_h[0]), "r"(ra_h[1]), "r"(ra_h[2]), "r"(ra_h[3]),
                      "r"(rb_h[2 * h]), "r"(rb_h[2 * h + 1]));
                asm volatile(
                    "mma.sync.aligned.m16n8k16.row.col.f32.bf16.bf16.f32 "
                    "{%0,%1,%2,%3},{%4,%5,%6,%7},{%8,%9},{%0,%1,%2,%3};"
                    : "+f"(A0[0]), "+f"(A0[1]), "+f"(A0[2]), "+f"(A0[3])
                    : "r"(ra_h[0]), "r"(ra_h[1]), "r"(ra_h[2]), "r"(ra_h[3]),
                      "r"(rb_l[2 * h]), "r"(rb_l[2 * h + 1]));
                asm volatile(
                    "mma.sync.aligned.m16n8k16.row.col.f32.bf16.bf16.f32 "
                    "{%0,%1,%2,%3},{%4,%5,%6,%7},{%8,%9},{%0,%1,%2,%3};"
                    : "+f"(A0[0]), "+f"(A0[1]), "+f"(A0[2]), "+f"(A0[3])
                    : "r"(ra_l[0]), "r"(ra_l[1]), "r"(ra_l[2]), "r"(ra_l[3]),
                      "r"(rb_h[2 * h]), "r"(rb_h[2 * h + 1]));
            }
        }
    }

    #pragma unroll
    for (int nt = 0; nt < 16; ++nt)
        #pragma unroll
        for (int q = 0; q < 4; ++q)
            acc[nt][q] = 1.0f / (1.0f + __expf(-acc[nt][q]));

    {
        float cs0[16], cs1[16];
        #pragma unroll
        for (int nt = 0; nt < 16; ++nt) {
            cs0[nt] = acc[nt][0] + acc[nt][2];
            cs1[nt] = acc[nt][1] + acc[nt][3];
        }
        #pragma unroll
        for (int s = 4; s <= 16; s <<= 1)
            #pragma unroll
            for (int nt = 0; nt < 16; ++nt) {
                cs0[nt] += __shfl_xor_sync(0xffffffffu, cs0[nt], s);
                cs1[nt] += __shfl_xor_sync(0xffffffffu, cs1[nt], s);
            }
        if (lane < 4) {
            #pragma unroll
            for (int nt = 0; nt < 16; ++nt)
                *(float2*)(table + w * 128 + nt * 8 + lane * 2) = make_float2(cs0[nt], cs1[nt]);
        }
    }
    __syncthreads();

    {
        int bb = tid >> 7, l = tid & 127;
        float s = table[(bb * 4 + 0) * 128 + l] + table[(bb * 4 + 1) * 128 + l]
                + table[(bb * 4 + 2) * 128 + l] + table[(bb * 4 + 3) * 128 + l];
        vbar[bb * 128 + l] = s * (1.0f / 64.0f);
    }
    __syncthreads();

    {
        int bb = w >> 2;
        float dis0 = 0.f, dis1 = 0.f;
        #pragma unroll
        for (int nt = 0; nt < 16; ++nt) {
            int c = nt * 8 + (lane & 3) * 2;
            float2 vb = *(const float2*)(vbar + bb * 128 + c);
            float d;
            d = acc[nt][0] - vb.x; dis0 = fmaf(d, d, dis0);
            d = acc[nt][1] - vb.y; dis0 = fmaf(d, d, dis0);
            d = acc[nt][2] - vb.x; dis1 = fmaf(d, d, dis1);
            d = acc[nt][3] - vb.y; dis1 = fmaf(d, d, dis1);
        }
        dis0 += __shfl_xor_sync(0xffffffffu, dis0, 1);
        dis0 += __shfl_xor_sync(0xffffffffu, dis0, 2);
        dis1 += __shfl_xor_sync(0xffffffffu, dis1, 1);
        dis1 += __shfl_xor_sync(0xffffffffu, dis1, 2);
        if ((lane & 3) == 0) {
            int row0 = m0 + (lane >> 2);
            float tw0 = thr[(row0 & 63) * N_ + n];
            float tw1 = thr[((row0 + 8) & 63) * N_ + n];
            wgt[row0]     = fmaxf(fmaf(tw0, tw0, -dis0 * (1.0f / L_)), 0.0f);
            wgt[row0 + 8] = fmaxf(fmaf(tw1, tw1, -dis1 * (1.0f / L_)), 0.0f);
        }
    }
    __syncthreads();

    if (tid < 128) {
        int bb = tid >> 6;
        float mxw = -3.0e38f;
        #pragma unroll 8
        for (int mm = 0; mm < 64; ++mm) mxw = fmaxf(mxw, wgt[bb * 64 + mm]);
        prob[tid] = __expf(wgt[tid] - mxw);
    }
    __syncthreads();

    if (tid < 128) {
        int bb = tid >> 6, t = tid & 63;
        const __nv_bfloat16* Ah = (const __nv_bfloat16*)smc;
        const __nv_bfloat16* Al = (const __nv_bfloat16*)(smc + 18432);
        float psum = 0.f;
        #pragma unroll 8
        for (int mm = 0; mm < 64; ++mm) psum += prob[bb * 64 + mm];
        float nc = 0.f;
        #pragma unroll 4
        for (int mm = 0; mm < 64; ++mm) {
            int row = bb * 64 + mm;
            float p = __bfloat162float(Ah[row * 72 + t]) + __bfloat162float(Al[row * 72 + t]);
            nc = fmaf(prob[bb * 64 + mm], p, nc);
        }
        ncs[tid] = nc / psum;
    }
    __syncthreads();

    if (tid < 128) {
        int bb = tid >> 6, t = tid & 63;
        float mu = 0.f;
        #pragma unroll 8
        for (int t2 = 0; t2 < T_; ++t2) mu += ncs[bb * 64 + t2];
        mu *= (1.0f / T_);
        float var = 0.f;
        #pragma unroll 8
        for (int t2 = 0; t2 < T_; ++t2) {
            float dv = ncs[bb * 64 + t2] - mu;
            var = fmaf(dv, dv, var);
        }
        var *= (1.0f / T_);
        float y = (ncs[tid] - mu) * rsqrtf(var + 1e-5f) * gamma[t] + beta[t];
        out[((size_t)(2 * bp + bb) * N_ + n) * T_ + t] = y;
    }
}

// ---------------------------------------------------------------------------
// Launch
// ---------------------------------------------------------------------------
extern "C" void kernel_launch(void* const* d_in, const int* in_sizes, int n_in,
                              void* d_out, int out_size) {
    const float* x      = (const float*)d_in[0];
    const float* rw     = (const float*)d_in[1];
    const float* thr    = (const float*)d_in[2];
    const float* leaves = (const float*)d_in[3];
    const float* gamma  = (const float*)d_in[4];
    const float* beta   = (const float*)d_in[5];
    float* out = (float*)d_out;

    static int attr_set = 0;
    if (!attr_set) {
        cudaFuncSetAttribute(k_priors_mma, cudaFuncAttributeMaxDynamicSharedMemorySize, KP_SMEM);
        cudaFuncSetAttribute(k_route, cudaFuncAttributeMaxDynamicSharedMemorySize, K3_SMEM);
        attr_set = 1;
    }

    k_leaves<<<1, 128>>>(leaves);
    k_xsplit<<<M_, 256>>>(x);
    k_entmax<<<M_ * N_, 128>>>(rw);
    k_priors_mma<<<M_ * 4, 256, KP_SMEM>>>();
    k_route<<<N_ * 128, 256, K3_SMEM>>>(thr, gamma, beta, out);
}